// round 15
// baseline (speedup 1.0000x reference)
#include <cuda_runtime.h>
#include <cuda_bf16.h>

// RPDC depthwise 5x5 conv via 8 taps of a 3x3 weight.
// x: (16,256,128,128) f32 -> out same shape.
//
// FINAL — converged at the mixed-r/w HBM ceiling (~6.25 TB/s, 78% of spec;
// kernel ~80us, bench ~88us incl. fixed harness overhead). Best: 88.13us.
//
// Design (validated over 14 rounds):
//  - one warp per (plane, 32-row strip); lane holds 4 columns (float4)
//  - vertical 5-row window in registers, fully unrolled (renaming, no MOVs)
//  - horizontal +/-2 halo via warp shuffles (no smem; L1 ~38%)
//  - 3-deep global-load lookahead (per-warp MLP covers DRAM latency)
//  - streaming stores (__stcs): output never re-read
//  - __launch_bounds__(256,4) pins 64 regs: every 48-reg variant tested
//    (R6/R7/R9/R11) lost ~10% DRAM throughput because ptxas schedules
//    loads next to their uses at 48 regs, regardless of occupancy gains.

#define W_DIM 128
#define H_DIM 128
#define TILE_H 32

__device__ __forceinline__ float4 ldrow(const float* __restrict__ xp, int gy, int lane) {
    if ((unsigned)gy < (unsigned)H_DIM)
        return __ldg(((const float4*)xp) + gy * (W_DIM / 4) + lane);
    return make_float4(0.f, 0.f, 0.f, 0.f);
}

// Expand lane's float4 (cols 4L..4L+3) into 8-float window (cols 4L-2..4L+5)
// via neighbor-lane shuffles. Lane 0 / 31 edges are zero padding.
#define EXPAND(dst, v)                                                  \
    {                                                                   \
        float _lz = __shfl_up_sync(0xffffffffu, (v).z, 1);              \
        float _lw = __shfl_up_sync(0xffffffffu, (v).w, 1);              \
        float _rx = __shfl_down_sync(0xffffffffu, (v).x, 1);            \
        float _ry = __shfl_down_sync(0xffffffffu, (v).y, 1);            \
        (dst)[0] = lane0 ? 0.f : _lz;                                   \
        (dst)[1] = lane0 ? 0.f : _lw;                                   \
        (dst)[2] = (v).x; (dst)[3] = (v).y;                             \
        (dst)[4] = (v).z; (dst)[5] = (v).w;                             \
        (dst)[6] = lane31 ? 0.f : _rx;                                  \
        (dst)[7] = lane31 ? 0.f : _ry;                                  \
    }

__global__ __launch_bounds__(256, 4) void rpdc_kernel(
    const float* __restrict__ x,
    const float* __restrict__ w,
    float* __restrict__ out)
{
    const int lane = threadIdx.x & 31;
    const int warp = threadIdx.x >> 5;
    const int item = blockIdx.x * 8 + warp;       // 0..16383
    const int plane = item >> 2;                  // n*256 + c
    const int y0 = (item & 3) * TILE_H;
    const int c = plane & 255;

    const float* xp = x + (size_t)plane * (H_DIM * W_DIM);
    float*       op = out + (size_t)plane * (H_DIM * W_DIM);

    const float* wp = w + c * 9;
    const float t0 = wp[1], t1 = wp[2], t2 = wp[3], t3 = wp[4];
    const float t4 = wp[5], t5 = wp[6], t6 = wp[7], t7 = wp[8];

    const bool lane0  = (lane == 0);
    const bool lane31 = (lane == 31);

    // a[k][j+2] = input col (4*lane + j), j in -2..5, window row k (y-2+k).
    float a[5][8];

    // Prologue: rows y0-2 .. y0+1 -> a[0..3]; lookahead rows y0+2..y0+4.
    #pragma unroll
    for (int k = 0; k < 4; ++k) {
        float4 v = ldrow(xp, y0 + k - 2, lane);
        EXPAND(a[k], v);
    }
    float4 nxt  = ldrow(xp, y0 + 2, lane);
    float4 nxt2 = ldrow(xp, y0 + 3, lane);
    float4 nxt3 = ldrow(xp, y0 + 4, lane);

    #pragma unroll
    for (int y = 0; y < TILE_H; ++y) {
        float4 cur = nxt;
        nxt = nxt2;
        nxt2 = nxt3;
        nxt3 = ldrow(xp, y0 + y + 5, lane);   // 3-deep lookahead
        EXPAND(a[4], cur);

        float4 o;
        #pragma unroll
        for (int j = 0; j < 4; ++j) {
            float acc;
            acc  = t0 * (a[0][j]     - a[1][j + 1]);
            acc += t1 * (a[0][j + 2] - a[1][j + 2]);
            acc += t2 * (a[0][j + 4] - a[1][j + 3]);
            acc += t3 * (a[2][j]     - a[2][j + 1]);
            acc += t4 * (a[2][j + 4] - a[2][j + 3]);
            acc += t5 * (a[4][j]     - a[3][j + 1]);
            acc += t6 * (a[4][j + 2] - a[3][j + 2]);
            acc += t7 * (a[4][j + 4] - a[3][j + 3]);
            ((float*)&o)[j] = acc;
        }
        // Streaming store: output never re-read; evict-first in L2.
        __stcs(((float4*)op) + (y0 + y) * (W_DIM / 4) + lane, o);

        // Roll window — fully unrolled, becomes register renaming.
        #pragma unroll
        for (int k = 0; k < 4; ++k)
            #pragma unroll
            for (int cc = 0; cc < 8; ++cc)
                a[k][cc] = a[k + 1][cc];
    }
}

extern "C" void kernel_launch(void* const* d_in, const int* in_sizes, int n_in,
                              void* d_out, int out_size)
{
    const float* x = (const float*)d_in[0];   // 16*256*128*128
    const float* w = (const float*)d_in[1];   // 256*1*3*3
    float* out = (float*)d_out;

    // 4096 planes * 4 row-tiles = 16384 warps / 8 warps per block
    dim3 grid(16 * 256 * 4 / 8);
    rpdc_kernel<<<grid, 256>>>(x, w, out);
}

// round 16
// speedup vs baseline: 1.0051x; 1.0051x over previous
#include <cuda_runtime.h>
#include <cuda_bf16.h>

// RPDC depthwise 5x5 conv via 8 taps of a 3x3 weight.
// x: (16,256,128,128) f32 -> out same shape.
//
// FINAL — converged at the mixed-r/w HBM ceiling (~6.25 TB/s, 78% of spec;
// kernel ~80us, bench ~88us incl. fixed harness overhead). Best: 88.13us.
//
// Design (validated over 15 rounds):
//  - one warp per (plane, 32-row strip); lane holds 4 columns (float4)
//  - vertical 5-row window in registers, fully unrolled (renaming, no MOVs)
//  - horizontal +/-2 halo via warp shuffles (no smem; L1 ~38%)
//  - 3-deep global-load lookahead (per-warp MLP covers DRAM latency)
//  - streaming stores (__stcs): output never re-read
//  - __launch_bounds__(256,4) pins 64 regs: every 48-reg variant tested
//    (R6/R7/R9/R11) lost ~10% DRAM throughput because ptxas schedules
//    loads next to their uses at 48 regs, regardless of occupancy gains.

#define W_DIM 128
#define H_DIM 128
#define TILE_H 32

__device__ __forceinline__ float4 ldrow(const float* __restrict__ xp, int gy, int lane) {
    if ((unsigned)gy < (unsigned)H_DIM)
        return __ldg(((const float4*)xp) + gy * (W_DIM / 4) + lane);
    return make_float4(0.f, 0.f, 0.f, 0.f);
}

// Expand lane's float4 (cols 4L..4L+3) into 8-float window (cols 4L-2..4L+5)
// via neighbor-lane shuffles. Lane 0 / 31 edges are zero padding.
#define EXPAND(dst, v)                                                  \
    {                                                                   \
        float _lz = __shfl_up_sync(0xffffffffu, (v).z, 1);              \
        float _lw = __shfl_up_sync(0xffffffffu, (v).w, 1);              \
        float _rx = __shfl_down_sync(0xffffffffu, (v).x, 1);            \
        float _ry = __shfl_down_sync(0xffffffffu, (v).y, 1);            \
        (dst)[0] = lane0 ? 0.f : _lz;                                   \
        (dst)[1] = lane0 ? 0.f : _lw;                                   \
        (dst)[2] = (v).x; (dst)[3] = (v).y;                             \
        (dst)[4] = (v).z; (dst)[5] = (v).w;                             \
        (dst)[6] = lane31 ? 0.f : _rx;                                  \
        (dst)[7] = lane31 ? 0.f : _ry;                                  \
    }

__global__ __launch_bounds__(256, 4) void rpdc_kernel(
    const float* __restrict__ x,
    const float* __restrict__ w,
    float* __restrict__ out)
{
    const int lane = threadIdx.x & 31;
    const int warp = threadIdx.x >> 5;
    const int item = blockIdx.x * 8 + warp;       // 0..16383
    const int plane = item >> 2;                  // n*256 + c
    const int y0 = (item & 3) * TILE_H;
    const int c = plane & 255;

    const float* xp = x + (size_t)plane * (H_DIM * W_DIM);
    float*       op = out + (size_t)plane * (H_DIM * W_DIM);

    const float* wp = w + c * 9;
    const float t0 = wp[1], t1 = wp[2], t2 = wp[3], t3 = wp[4];
    const float t4 = wp[5], t5 = wp[6], t6 = wp[7], t7 = wp[8];

    const bool lane0  = (lane == 0);
    const bool lane31 = (lane == 31);

    // a[k][j+2] = input col (4*lane + j), j in -2..5, window row k (y-2+k).
    float a[5][8];

    // Prologue: rows y0-2 .. y0+1 -> a[0..3]; lookahead rows y0+2..y0+4.
    #pragma unroll
    for (int k = 0; k < 4; ++k) {
        float4 v = ldrow(xp, y0 + k - 2, lane);
        EXPAND(a[k], v);
    }
    float4 nxt  = ldrow(xp, y0 + 2, lane);
    float4 nxt2 = ldrow(xp, y0 + 3, lane);
    float4 nxt3 = ldrow(xp, y0 + 4, lane);

    #pragma unroll
    for (int y = 0; y < TILE_H; ++y) {
        float4 cur = nxt;
        nxt = nxt2;
        nxt2 = nxt3;
        nxt3 = ldrow(xp, y0 + y + 5, lane);   // 3-deep lookahead
        EXPAND(a[4], cur);

        float4 o;
        #pragma unroll
        for (int j = 0; j < 4; ++j) {
            float acc;
            acc  = t0 * (a[0][j]     - a[1][j + 1]);
            acc += t1 * (a[0][j + 2] - a[1][j + 2]);
            acc += t2 * (a[0][j + 4] - a[1][j + 3]);
            acc += t3 * (a[2][j]     - a[2][j + 1]);
            acc += t4 * (a[2][j + 4] - a[2][j + 3]);
            acc += t5 * (a[4][j]     - a[3][j + 1]);
            acc += t6 * (a[4][j + 2] - a[3][j + 2]);
            acc += t7 * (a[4][j + 4] - a[3][j + 3]);
            ((float*)&o)[j] = acc;
        }
        // Streaming store: output never re-read; evict-first in L2.
        __stcs(((float4*)op) + (y0 + y) * (W_DIM / 4) + lane, o);

        // Roll window — fully unrolled, becomes register renaming.
        #pragma unroll
        for (int k = 0; k < 4; ++k)
            #pragma unroll
            for (int cc = 0; cc < 8; ++cc)
                a[k][cc] = a[k + 1][cc];
    }
}

extern "C" void kernel_launch(void* const* d_in, const int* in_sizes, int n_in,
                              void* d_out, int out_size)
{
    const float* x = (const float*)d_in[0];   // 16*256*128*128
    const float* w = (const float*)d_in[1];   // 256*1*3*3
    float* out = (float*)d_out;

    // 4096 planes * 4 row-tiles = 16384 warps / 8 warps per block
    dim3 grid(16 * 256 * 4 / 8);
    rpdc_kernel<<<grid, 256>>>(x, w, out);
}

// round 17
// speedup vs baseline: 1.0065x; 1.0015x over previous
#include <cuda_runtime.h>
#include <cuda_bf16.h>

// RPDC depthwise 5x5 conv via 8 taps of a 3x3 weight.
// x: (16,256,128,128) f32 -> out same shape.
//
// FINAL — converged at the mixed-r/w HBM ceiling (~6.28 TB/s, 78.5% of spec;
// kernel ~80us, bench ~88us incl. fixed harness overhead). Best: 88.10us.
//
// Design (validated over 16 rounds, confirmed x5):
//  - one warp per (plane, 32-row strip); lane holds 4 columns (float4)
//  - vertical 5-row window in registers, fully unrolled (renaming, no MOVs)
//  - horizontal +/-2 halo via warp shuffles (no smem; L1 ~38%)
//  - 3-deep global-load lookahead (per-warp MLP covers DRAM latency)
//  - streaming stores (__stcs): output never re-read
//  - __launch_bounds__(256,4) pins 64 regs (= exactly fills the 64K regfile
//    at 4x256 threads): every 48-reg variant tested (R6/R7/R9/R11) lost
//    ~10% DRAM throughput because ptxas stops hoisting loads at 48 regs,
//    regardless of occupancy gains.

#define W_DIM 128
#define H_DIM 128
#define TILE_H 32

__device__ __forceinline__ float4 ldrow(const float* __restrict__ xp, int gy, int lane) {
    if ((unsigned)gy < (unsigned)H_DIM)
        return __ldg(((const float4*)xp) + gy * (W_DIM / 4) + lane);
    return make_float4(0.f, 0.f, 0.f, 0.f);
}

// Expand lane's float4 (cols 4L..4L+3) into 8-float window (cols 4L-2..4L+5)
// via neighbor-lane shuffles. Lane 0 / 31 edges are zero padding.
#define EXPAND(dst, v)                                                  \
    {                                                                   \
        float _lz = __shfl_up_sync(0xffffffffu, (v).z, 1);              \
        float _lw = __shfl_up_sync(0xffffffffu, (v).w, 1);              \
        float _rx = __shfl_down_sync(0xffffffffu, (v).x, 1);            \
        float _ry = __shfl_down_sync(0xffffffffu, (v).y, 1);            \
        (dst)[0] = lane0 ? 0.f : _lz;                                   \
        (dst)[1] = lane0 ? 0.f : _lw;                                   \
        (dst)[2] = (v).x; (dst)[3] = (v).y;                             \
        (dst)[4] = (v).z; (dst)[5] = (v).w;                             \
        (dst)[6] = lane31 ? 0.f : _rx;                                  \
        (dst)[7] = lane31 ? 0.f : _ry;                                  \
    }

__global__ __launch_bounds__(256, 4) void rpdc_kernel(
    const float* __restrict__ x,
    const float* __restrict__ w,
    float* __restrict__ out)
{
    const int lane = threadIdx.x & 31;
    const int warp = threadIdx.x >> 5;
    const int item = blockIdx.x * 8 + warp;       // 0..16383
    const int plane = item >> 2;                  // n*256 + c
    const int y0 = (item & 3) * TILE_H;
    const int c = plane & 255;

    const float* xp = x + (size_t)plane * (H_DIM * W_DIM);
    float*       op = out + (size_t)plane * (H_DIM * W_DIM);

    const float* wp = w + c * 9;
    const float t0 = wp[1], t1 = wp[2], t2 = wp[3], t3 = wp[4];
    const float t4 = wp[5], t5 = wp[6], t6 = wp[7], t7 = wp[8];

    const bool lane0  = (lane == 0);
    const bool lane31 = (lane == 31);

    // a[k][j+2] = input col (4*lane + j), j in -2..5, window row k (y-2+k).
    float a[5][8];

    // Prologue: rows y0-2 .. y0+1 -> a[0..3]; lookahead rows y0+2..y0+4.
    #pragma unroll
    for (int k = 0; k < 4; ++k) {
        float4 v = ldrow(xp, y0 + k - 2, lane);
        EXPAND(a[k], v);
    }
    float4 nxt  = ldrow(xp, y0 + 2, lane);
    float4 nxt2 = ldrow(xp, y0 + 3, lane);
    float4 nxt3 = ldrow(xp, y0 + 4, lane);

    #pragma unroll
    for (int y = 0; y < TILE_H; ++y) {
        float4 cur = nxt;
        nxt = nxt2;
        nxt2 = nxt3;
        nxt3 = ldrow(xp, y0 + y + 5, lane);   // 3-deep lookahead
        EXPAND(a[4], cur);

        float4 o;
        #pragma unroll
        for (int j = 0; j < 4; ++j) {
            float acc;
            acc  = t0 * (a[0][j]     - a[1][j + 1]);
            acc += t1 * (a[0][j + 2] - a[1][j + 2]);
            acc += t2 * (a[0][j + 4] - a[1][j + 3]);
            acc += t3 * (a[2][j]     - a[2][j + 1]);
            acc += t4 * (a[2][j + 4] - a[2][j + 3]);
            acc += t5 * (a[4][j]     - a[3][j + 1]);
            acc += t6 * (a[4][j + 2] - a[3][j + 2]);
            acc += t7 * (a[4][j + 4] - a[3][j + 3]);
            ((float*)&o)[j] = acc;
        }
        // Streaming store: output never re-read; evict-first in L2.
        __stcs(((float4*)op) + (y0 + y) * (W_DIM / 4) + lane, o);

        // Roll window — fully unrolled, becomes register renaming.
        #pragma unroll
        for (int k = 0; k < 4; ++k)
            #pragma unroll
            for (int cc = 0; cc < 8; ++cc)
                a[k][cc] = a[k + 1][cc];
    }
}

extern "C" void kernel_launch(void* const* d_in, const int* in_sizes, int n_in,
                              void* d_out, int out_size)
{
    const float* x = (const float*)d_in[0];   // 16*256*128*128
    const float* w = (const float*)d_in[1];   // 256*1*3*3
    float* out = (float*)d_out;

    // 4096 planes * 4 row-tiles = 16384 warps / 8 warps per block
    dim3 grid(16 * 256 * 4 / 8);
    rpdc_kernel<<<grid, 256>>>(x, w, out);
}